// round 17
// baseline (speedup 1.0000x reference)
#include <cuda_runtime.h>
#include <math.h>
#include <stdint.h>

#define B   128
#define T   256
#define H   512
#define H4  2048
#define V   128
#define LW  32
#define SOS 1
#define BH  (B*H)
#define NBLK 128
#define NTHR 512

__device__ float g_enc0[(size_t)B*T*2*H];
__device__ float g_enc1[(size_t)B*T*2*H];
__device__ float g_h0[2*2*BH];
__device__ float g_h1[2*2*BH];
__device__ float g_c0[2*BH];
__device__ float g_c1[2*BH];
__device__ float g_dech[2*2*BH];
__device__ float g_decc[2*BH];
__device__ float g_ctx[B*2*H];
__device__ float g_gpart[(size_t)B*H4];
__device__ float g_queryP[2][B*2*H];
__device__ float g_combP[3][B*H];
__device__ int   g_tok[B];

// tf32 weights (hi/lo): [0,2097152)=w0hh[dir][512][2048];
// [2097152,8388608)=L1[dir][1536][2048] rows 0..1023=w1ih,1024..1535=w1hh
#define WCONV_N 8388608
__device__ float g_wHi[WCONV_N];
__device__ float g_wLo[WCONV_N];
// encoder gate partials [ks*2+dir][128 m][2048 gatecol]
__device__ float g_epart[8*128*2048];

__device__ unsigned g_cnt = 0;
__device__ volatile unsigned g_gen = 0;

__device__ __forceinline__ void gbar(unsigned &gen)
{
    __syncthreads();
    if (threadIdx.x == 0) {
        __threadfence();
        unsigned t = atomicAdd(&g_cnt, 1u);
        if (t == NBLK - 1u) {
            atomicExch(&g_cnt, 0u);
            __threadfence();
            g_gen = gen + 1u;
        } else {
            while (g_gen == gen) {}
            __threadfence();
        }
    }
    __syncthreads();
    gen++;
}

__device__ __forceinline__ uint32_t f2tf(float v)
{
    uint32_t r;
    asm("cvt.rna.tf32.f32 %0, %1;" : "=r"(r) : "f"(v));
    return r;
}

__device__ __forceinline__ void mma_tf32(
    float c[4], uint32_t a0, uint32_t a1, uint32_t a2, uint32_t a3,
    uint32_t b0, uint32_t b1)
{
    asm("mma.sync.aligned.m16n8k8.row.col.f32.tf32.tf32.f32 "
        "{%0,%1,%2,%3}, {%4,%5,%6,%7}, {%8,%9}, {%0,%1,%2,%3};"
        : "+f"(c[0]), "+f"(c[1]), "+f"(c[2]), "+f"(c[3])
        : "r"(a0), "r"(a1), "r"(a2), "r"(a3), "r"(b0), "r"(b1));
}

// SMEM: enc frag bufs [0..8192): Ahi 0, Alo 2048, Bhi 4096, Blo 6144
// decoder mm84 uses [0..8192), GS[64][64] at 8192
#define SH_FLOATS 12288

// ---------------- decoder fp32 GEMM (unchanged) ----------------
__device__ __forceinline__ void mm84(
    float acc[8][4],
    const float* __restrict__ A, long lda, const int* __restrict__ idx, int m0,
    const float* __restrict__ W, long ldw, int gateu0, int n0, int K,
    float* __restrict__ SH)
{
    const int tid = threadIdx.x;
    const int gid = tid >> 7;
    const int g   = tid & 127;
    float* as_ = SH + gid * 2048;
    float* bs_ = SH + gid * 2048 + 1024;
    const int Kq   = K >> 2;
    const int koff = gid * Kq;
    const int NC   = Kq >> 3;
    const int lrow = g >> 1, lseg = (g & 1) * 4;
    long arow = idx ? (long)idx[m0 + lrow] : (long)(m0 + lrow);
    const float* Ab = A + arow * lda + koff + lseg;
    const int bk = g >> 4, bn4 = (g & 15) * 4;
    const int col = (gateu0 >= 0) ? ((bn4 >> 4) * H + gateu0 + (bn4 & 15))
                                  : (n0 + bn4);
    const float* Wb = W + (long)(koff + bk) * ldw + col;
    const int my = g >> 4, nx = g & 15;

    float4 av = *(const float4*)Ab;
    float4 bv = *(const float4*)Wb;
    as_[(lseg+0)*64 + lrow] = av.x; as_[(lseg+1)*64 + lrow] = av.y;
    as_[(lseg+2)*64 + lrow] = av.z; as_[(lseg+3)*64 + lrow] = av.w;
    *(float4*)(bs_ + bk*64 + bn4) = bv;
    __syncthreads();
    int cur = 0;
    for (int ch = 0; ch < NC; ch++) {
        if (ch + 1 < NC) {
            av = *(const float4*)(Ab + (ch + 1) * 8);
            bv = *(const float4*)(Wb + (long)(ch + 1) * 8 * ldw);
        }
        const float* ab = as_ + cur * 512;
        const float* bb = bs_ + cur * 512;
        #pragma unroll
        for (int k = 0; k < 8; k++) {
            float4 b4 = *(const float4*)(bb + k*64 + nx*4);
            float4 a0 = *(const float4*)(ab + k*64 + my*8);
            float4 a1 = *(const float4*)(ab + k*64 + my*8 + 4);
            float aa[8] = {a0.x,a0.y,a0.z,a0.w,a1.x,a1.y,a1.z,a1.w};
            float bbv[4] = {b4.x,b4.y,b4.z,b4.w};
            #pragma unroll
            for (int i = 0; i < 8; i++)
                #pragma unroll
                for (int j = 0; j < 4; j++)
                    acc[i][j] = fmaf(aa[i], bbv[j], acc[i][j]);
        }
        if (ch + 1 < NC) {
            int nxt = cur ^ 1;
            float* an = as_ + nxt * 512;
            float* bn_ = bs_ + nxt * 512;
            an[(lseg+0)*64 + lrow] = av.x; an[(lseg+1)*64 + lrow] = av.y;
            an[(lseg+2)*64 + lrow] = av.z; an[(lseg+3)*64 + lrow] = av.w;
            *(float4*)(bn_ + bk*64 + bn4) = bv;
            __syncthreads();
            cur = nxt;
        }
    }
}

__device__ __forceinline__ void reduce_groups(float acc[8][4], float* __restrict__ GSf)
{
    float (*GS)[64] = (float (*)[64])GSf;
    const int tid = threadIdx.x;
    const int gid = tid >> 7, g = tid & 127;
    const int my = g >> 4, nx = g & 15;
    #pragma unroll
    for (int pg = 3; pg >= 0; pg--) {
        if (gid == pg) {
            #pragma unroll
            for (int i = 0; i < 8; i++)
                #pragma unroll
                for (int j = 0; j < 4; j++) {
                    if (pg == 3) GS[my*8+i][nx*4+j]  = acc[i][j];
                    else         GS[my*8+i][nx*4+j] += acc[i][j];
                }
        }
        __syncthreads();
    }
}

__device__ __forceinline__ float sigm(float v) { return 1.f/(1.f + expf(-v)); }

// ---------------- encoder frag loaders ----------------
__device__ __forceinline__ void enc_loadA(
    float av[4], int layer, int t, int po, int dir, int kg)
{
    const float* ap; long astr; int kl;
    if (layer == 0)      { ap = g_h0 + po + (long)dir*BH; astr = H;           kl = kg; }
    else if (kg < 1024)  { ap = g_enc0 + (long)t*2*H;     astr = (long)T*2*H; kl = kg; }
    else                 { ap = g_h1 + po + (long)dir*BH; astr = H;           kl = kg - 1024; }
    const int lane = threadIdx.x & 31;
    const int mrow = ((threadIdx.x >> 5) << 4) + (lane >> 2);
    const int k = kl + (lane & 3);
    av[0] = ap[(long)mrow*astr + k];
    av[1] = ap[(long)(mrow+8)*astr + k];
    av[2] = ap[(long)mrow*astr + k + 4];
    av[3] = ap[(long)(mrow+8)*astr + k + 4];
}

__device__ __forceinline__ void enc_loadB(float bv[4], long wbase, int kg, int colB)
{
    const int tq = threadIdx.x & 3;
    long r0 = wbase + (long)(kg + tq) * H4 + colB;
    long r1 = wbase + (long)(kg + tq + 4) * H4 + colB;
    bv[0] = g_wHi[r0]; bv[1] = g_wHi[r1];
    bv[2] = g_wLo[r0]; bv[3] = g_wLo[r1];
}

__device__ __forceinline__ void enc_storeA(const float av[4], int buf, float* SH)
{
    uint4 hi, lo;
    hi.x = f2tf(av[0]); lo.x = f2tf(av[0] - __uint_as_float(hi.x));
    hi.y = f2tf(av[1]); lo.y = f2tf(av[1] - __uint_as_float(hi.y));
    hi.z = f2tf(av[2]); lo.z = f2tf(av[2] - __uint_as_float(hi.z));
    hi.w = f2tf(av[3]); lo.w = f2tf(av[3] - __uint_as_float(hi.w));
    const int off = (buf*8 + (threadIdx.x >> 5)) * 128 + (threadIdx.x & 31) * 4;
    *(uint4*)&SH[off]        = hi;
    *(uint4*)&SH[2048 + off] = lo;
}

__device__ __forceinline__ void enc_storeB(const float bv[4], int buf, float* SH)
{
    const int off = (buf*16 + (threadIdx.x >> 5)) * 64 + (threadIdx.x & 31) * 2;
    *(float2*)&SH[4096 + off] = make_float2(bv[0], bv[1]);
    *(float2*)&SH[6144 + off] = make_float2(bv[2], bv[3]);
}

// ---------------- persistent kernel ----------------
__global__ void __launch_bounds__(NTHR, 1)
traj_kernel(const float* __restrict__ x,
            const float* __restrict__ w0ih, const float* __restrict__ w0hh, const float* __restrict__ b0,
            const float* __restrict__ w1ih, const float* __restrict__ w1hh, const float* __restrict__ b1,
            const float* __restrict__ dWih, const float* __restrict__ dWhh, const float* __restrict__ db,
            const float* __restrict__ emb,
            const float* __restrict__ Wq,  const float* __restrict__ bq,
            const float* __restrict__ Wc,  const float* __restrict__ bc,
            const float* __restrict__ Wf,  const float* __restrict__ bfv,
            float* __restrict__ out)
{
    __shared__ __align__(16) float SH[SH_FLOATS];
    float* GSf = SH + 8192;
    float (*GS)[64] = (float (*)[64])GSf;

    const int blk = blockIdx.x;
    const int tid = threadIdx.x;
    unsigned gen = 0;

    // ---- init: zero states + weight conversion ----
    for (int i = blk*NTHR + tid; i < 2*BH; i += NBLK*NTHR) {
        g_h0[i] = 0.f; g_h1[i] = 0.f;
        g_c0[i] = 0.f; g_c1[i] = 0.f;
    }
    for (int i = blk*NTHR + tid; i < WCONV_N; i += NBLK*NTHR) {
        float v;
        if (i < 2097152) v = w0hh[i];
        else {
            int j = i - 2097152;
            int d = j / 3145728;
            int rem = j - d * 3145728;
            int rr = rem >> 11, c = rem & 2047;
            v = (rr < 1024) ? w1ih[((long)d*1024 + rr)*2048 + c]
                            : w1hh[((long)d*512 + (rr - 1024))*2048 + c];
        }
        uint32_t hv = f2tf(v);
        g_wHi[i] = __uint_as_float(hv);
        g_wLo[i] = __uint_as_float(f2tf(v - __uint_as_float(hv)));
    }
    gbar(gen);

    // ---- encoder: tf32 MMA, block = (dir, ks, ut) ----
    {
        const int dir = blk >> 6;
        const int ks  = (blk >> 4) & 3;
        const int u0  = (blk & 15) * 32;
        const int warp = tid >> 5, lane = tid & 31;
        const int wy = warp >> 2, wx = warp & 3;
        const int g  = lane >> 2, tq = lane & 3;
        const int nB   = warp * 8 + g;
        const int colB = (nB >> 5) * H + u0 + (nB & 31);
        float* ep = g_epart + (long)(ks*2 + dir) * 128 * 2048;

        for (int layer = 0; layer < 2; layer++) {
            const float* bias_d = (layer ? b1 : b0) + (long)dir*H4;
            const float* Wi     = w0ih + (long)dir*2*H4;
            float* cB = (layer ? g_c1 : g_c0) + (long)dir*BH;
            float* y  = layer ? g_enc1 : g_enc0;
            const long wbase = layer ? (2097152 + (long)dir*3145728)
                                     : ((long)dir*1048576);
            const int NCk = layer ? 48 : 16;
            const int kb  = ks * (layer ? 384 : 128);

            for (int tf = 0; tf < T; tf++) {
                const int t  = dir ? (T - 1 - tf) : tf;
                const int po = (tf & 1) * 2 * BH;
                const int pn = ((tf + 1) & 1) * 2 * BH;

                float C[2][4][4];
                #pragma unroll
                for (int a2 = 0; a2 < 2; a2++)
                    #pragma unroll
                    for (int b2 = 0; b2 < 4; b2++)
                        #pragma unroll
                        for (int c2 = 0; c2 < 4; c2++)
                            C[a2][b2][c2] = 0.f;

                float av[4] = {0,0,0,0};
                float bv[4];
                if (tid < 256) enc_loadA(av, layer, t, po, dir, kb);
                enc_loadB(bv, wbase, kb, colB);
                if (tid < 256) enc_storeA(av, 0, SH);
                enc_storeB(bv, 0, SH);
                __syncthreads();

                int cur = 0;
                for (int ci = 0; ci < NCk; ci++) {
                    if (ci + 1 < NCk) {
                        int kg = kb + (ci + 1) * 8;
                        if (tid < 256) enc_loadA(av, layer, t, po, dir, kg);
                        enc_loadB(bv, wbase, kg, colB);
                    }
                    #pragma unroll
                    for (int mt = 0; mt < 2; mt++) {
                        uint4 ah = *(uint4*)&SH[(cur*8 + wy*2 + mt)*128 + lane*4];
                        uint4 al = *(uint4*)&SH[2048 + (cur*8 + wy*2 + mt)*128 + lane*4];
                        #pragma unroll
                        for (int ni = 0; ni < 4; ni++) {
                            int n8 = wx*4 + ni;
                            uint2 bh = *(uint2*)&SH[4096 + (cur*16 + n8)*64 + lane*2];
                            uint2 bl = *(uint2*)&SH[6144 + (cur*16 + n8)*64 + lane*2];
                            mma_tf32(C[mt][ni], ah.x, ah.y, ah.z, ah.w, bh.x, bh.y);
                            mma_tf32(C[mt][ni], ah.x, ah.y, ah.z, ah.w, bl.x, bl.y);
                            mma_tf32(C[mt][ni], al.x, al.y, al.z, al.w, bh.x, bh.y);
                        }
                    }
                    if (ci + 1 < NCk) {
                        int nxt = cur ^ 1;
                        if (tid < 256) enc_storeA(av, nxt, SH);
                        enc_storeB(bv, nxt, SH);
                        __syncthreads();
                        cur = nxt;
                    }
                }

                // write partial: gate = wx, col = u0 + ni*8 + 2tq
                #pragma unroll
                for (int mt = 0; mt < 2; mt++) {
                    int m = wy*32 + mt*16 + g;
                    #pragma unroll
                    for (int ni = 0; ni < 4; ni++) {
                        long base = (long)m*2048 + wx*H + u0 + ni*8 + 2*tq;
                        *(float2*)(ep + base) = make_float2(C[mt][ni][0], C[mt][ni][1]);
                        *(float2*)(ep + base + 8*2048) = make_float2(C[mt][ni][2], C[mt][ni][3]);
                    }
                }
                gbar(gen);

                // update: rows ks*32..+31, u0..u0+31
                float* hN = (layer ? g_h1 : g_h0) + pn + (long)dir*BH;
                #pragma unroll
                for (int r = 0; r < 2; r++) {
                    int e  = tid + r*NTHR;           // < 1024
                    int ml = e >> 5, ui = e & 31;
                    int mr = ks*32 + ml, u = u0 + ui;
                    float gv[4];
                    #pragma unroll
                    for (int gi2 = 0; gi2 < 4; gi2++) {
                        float sacc = bias_d[gi2*512 + u];
                        #pragma unroll
                        for (int p = 0; p < 4; p++)
                            sacc += g_epart[((long)(p*2 + dir)*128 + mr)*2048 + gi2*512 + u];
                        gv[gi2] = sacc;
                    }
                    if (layer == 0) {
                        float x0 = x[((long)mr*T + t)*2 + 0];
                        float x1 = x[((long)mr*T + t)*2 + 1];
                        gv[0] += x0*Wi[u]      + x1*Wi[H4 + u];
                        gv[1] += x0*Wi[512+u]  + x1*Wi[H4 + 512+u];
                        gv[2] += x0*Wi[1024+u] + x1*Wi[H4 + 1024+u];
                        gv[3] += x0*Wi[1536+u] + x1*Wi[H4 + 1536+u];
                    }
                    long su = (long)mr*H + u;
                    float cn = sigm(gv[1])*cB[su] + sigm(gv[0])*tanhf(gv[2]);
                    float hn = sigm(gv[3])*tanhf(cn);
                    cB[su] = cn;
                    hN[su] = hn;
                    y[((long)mr*T + t)*(2*H) + dir*H + u] = hn;
                }
                gbar(gen);
            }
        }
    }

    // ---- decoder init ----
    for (int i = blk*NTHR + tid; i < BH; i += NBLK*NTHR) {
        g_dech[i]      = g_h0[i] + g_h0[BH + i];
        g_decc[i]      = g_c0[i] + g_c0[BH + i];
        g_dech[BH + i] = g_h1[i] + g_h1[BH + i];
        g_decc[BH + i] = g_c1[i] + g_c1[BH + i];
    }
    if (blk == 0 && tid < B) g_tok[tid] = SOS;
    gbar(gen);

    // ---- decoder: 32 greedy steps (fp32 path, unchanged) ----
    for (int s = 0; s < LW; s++) {
        const int po = (s & 1) * 2 * BH;
        const int pn = ((s + 1) & 1) * 2 * BH;

        for (int l = 0; l < 2; l++) {
            const int w  = blk >> 6;
            const int m0 = ((blk >> 5) & 1) * 64;
            const int u0 = (blk & 31) * 16;
            float acc[8][4] = {};
            if (w == 0) {
                if (l == 0)
                    mm84(acc, emb, H, g_tok, m0, dWih, H4, u0, 0, H, SH);
                else
                    mm84(acc, g_dech + pn, H, nullptr, m0,
                         dWih + (long)H*H4, H4, u0, 0, H, SH);
            } else {
                mm84(acc, g_dech + po + (long)l*BH, H, nullptr, m0,
                     dWhh + (long)l*H*H4, H4, u0, 0, H, SH);
            }
            reduce_groups(acc, GSf);
            if (w == 0) {
                #pragma unroll
                for (int r = 0; r < 8; r++) {
                    int e = tid + r*NTHR;
                    int mrow = e >> 6, ncol = e & 63;
                    int col = (ncol >> 4)*H + u0 + (ncol & 15);
                    g_gpart[(long)(m0 + mrow)*H4 + col] = GS[mrow][ncol];
                }
            }
            gbar(gen);
            if (w == 1) {
                const float* bias_d = db + (long)l*H4;
                float* hN = g_dech + pn + (long)l*BH;
                float* cB = g_decc + (long)l*BH;
                #pragma unroll
                for (int r = 0; r < 2; r++) {
                    int e = tid + r*NTHR;
                    int ml = e >> 4, ui = e & 15;
                    int u = u0 + ui, m = m0 + ml;
                    const float* gp = g_gpart + (long)m*H4;
                    float gi = GS[ml][ui]    + gp[u]      + bias_d[u];
                    float gf = GS[ml][16+ui] + gp[512+u]  + bias_d[512+u];
                    float gg = GS[ml][32+ui] + gp[1024+u] + bias_d[1024+u];
                    float go = GS[ml][48+ui] + gp[1536+u] + bias_d[1536+u];
                    long su = (long)m*H + u;
                    float cn = sigm(gf)*cB[su] + sigm(gi)*tanhf(gg);
                    float hn = sigm(go)*tanhf(cn);
                    cB[su] = cn;
                    hN[su] = hn;
                }
            }
            gbar(gen);
        }

        if (blk < 64) {
            const int part = blk >> 5;
            const int q  = blk & 31;
            const int m0 = (q >> 4) * 64;
            const int n0 = (q & 15) * 64;
            float acc[8][4] = {};
            mm84(acc, g_dech + pn + BH + part*256, H, nullptr, m0,
                 Wq + (long)(part*256)*(2*H), 2*H, -1, n0, 256, SH);
            reduce_groups(acc, GSf);
            #pragma unroll
            for (int r = 0; r < 8; r++) {
                int e = tid + r*NTHR;
                int mrow = e >> 6, ncol = e & 63;
                g_queryP[part][(long)(m0 + mrow)*(2*H) + n0 + ncol] = GS[mrow][ncol];
            }
        }
        gbar(gen);

        {
            const int b = blk;
            float* qs  = GSf;
            float* sc  = GSf + 1024;
            float* red = GSf + 1280;
            for (int e = tid; e < 2*H; e += NTHR)
                qs[e] = g_queryP[0][(long)b*2*H + e] + g_queryP[1][(long)b*2*H + e] + bq[e];
            __syncthreads();
            const int warp = tid >> 5, lane = tid & 31;
            for (int tb = 0; tb < T; tb += 16) {
                int t = tb + warp;
                const float* row = g_enc1 + ((long)b*T + t)*(2*H);
                float p = 0.f;
                for (int e = lane; e < 2*H; e += 32) p = fmaf(row[e], qs[e], p);
                #pragma unroll
                for (int o = 16; o; o >>= 1) p += __shfl_xor_sync(0xffffffffu, p, o);
                if (lane == 0) sc[t] = p;
            }
            __syncthreads();
            float v = (tid < T) ? sc[tid] : -1e30f;
            red[tid] = v; __syncthreads();
            for (int o = 256; o; o >>= 1) {
                if (tid < o) red[tid] = fmaxf(red[tid], red[tid + o]);
                __syncthreads();
            }
            float mx = red[0]; __syncthreads();
            float e = expf(v - mx);
            red[tid] = (tid < T) ? e : 0.f; __syncthreads();
            for (int o = 256; o; o >>= 1) {
                if (tid < o) red[tid] += red[tid + o];
                __syncthreads();
            }
            if (tid < T) {
                float a = e / red[0];
                sc[tid] = a;
                out[786432 + ((long)b*T + tid)*LW + s] = a;
            }
            __syncthreads();
            for (int ec = tid; ec < 2*H; ec += NTHR) {
                float accv = 0.f;
                const float* base = g_enc1 + ((long)b*T)*(2*H) + ec;
                for (int t = 0; t < T; t++) accv = fmaf(sc[t], base[(long)t*2*H], accv);
                g_ctx[(long)b*2*H + ec] = accv;
            }
        }
        gbar(gen);

        if (blk < 48) {
            const int part = blk >> 4;
            const int q  = blk & 15;
            const int m0 = (q >> 3) * 64;
            const int n0 = (q & 7) * 64;
            float acc[8][4] = {};
            if (part == 0)
                mm84(acc, g_dech + pn + BH, H, nullptr, m0, Wc, H, -1, n0, 512, SH);
            else if (part == 1)
                mm84(acc, g_ctx, 2*H, nullptr, m0, Wc + (long)512*H, H, -1, n0, 512, SH);
            else
                mm84(acc, g_ctx + 512, 2*H, nullptr, m0, Wc + (long)1024*H, H, -1, n0, 512, SH);
            reduce_groups(acc, GSf);
            #pragma unroll
            for (int r = 0; r < 8; r++) {
                int e = tid + r*NTHR;
                int mrow = e >> 6, ncol = e & 63;
                g_combP[part][(long)(m0 + mrow)*H + n0 + ncol] = GS[mrow][ncol];
            }
        }
        gbar(gen);

        {
            const int b = blk;
            float* cs = GSf;
            float* sv = GSf + 512;
            int*   si = (int*)(GSf + 640);
            for (int k = tid; k < H; k += NTHR)
                cs[k] = g_combP[0][(long)b*H + k] + g_combP[1][(long)b*H + k]
                      + g_combP[2][(long)b*H + k] + bc[k];
            __syncthreads();
            if (tid < V) {
                float acc = bfv[tid];
                for (int k = 0; k < H; k++) acc = fmaf(cs[k], Wf[(long)k*V + tid], acc);
                out[((long)b*LW + s)*V + tid] = acc;
                sv[tid] = acc; si[tid] = tid;
            }
            __syncthreads();
            for (int o = 64; o; o >>= 1) {
                if (tid < o) {
                    float v2 = sv[tid + o]; int i2 = si[tid + o];
                    if (v2 > sv[tid] || (v2 == sv[tid] && i2 < si[tid])) {
                        sv[tid] = v2; si[tid] = i2;
                    }
                }
                __syncthreads();
            }
            if (tid == 0) g_tok[b] = si[0];
        }
        gbar(gen);
    }

    for (int i = blk*NTHR + tid; i < 2*BH; i += NBLK*NTHR) {
        out[524288 + i] = g_dech[i];
        out[655360 + i] = g_decc[i];
    }
}

extern "C" void kernel_launch(void* const* d_in, const int* in_sizes, int n_in,
                              void* d_out, int out_size)
{
    (void)in_sizes; (void)n_in; (void)out_size;
    traj_kernel<<<NBLK, NTHR>>>(
        (const float*)d_in[0],  (const float*)d_in[1],  (const float*)d_in[2],
        (const float*)d_in[3],  (const float*)d_in[4],  (const float*)d_in[5],
        (const float*)d_in[6],  (const float*)d_in[7],  (const float*)d_in[8],
        (const float*)d_in[9],  (const float*)d_in[10], (const float*)d_in[11],
        (const float*)d_in[12], (const float*)d_in[13], (const float*)d_in[14],
        (const float*)d_in[15], (const float*)d_in[16], (float*)d_out);
}